// round 15
// baseline (speedup 1.0000x reference)
#include <cuda_runtime.h>
#include <cuda_bf16.h>
#include <math.h>

// Problem constants
#define B_    8
#define N_    128
#define K_    16
#define ALPHA 0.01f
#define LAM   1.0f
#define KAPPA 1.0f
#define EPS   1e-6f

#define NODES (B_ * N_)   // 1024
#define WPB   4           // warps (nodes) per block in prep
#define PST   20          // padded row stride (floats) for prep matrices

// ---- packed f32x2 helpers (sm_100+ PTX) ----
#define FMA2(d, a, b, c) \
    asm("fma.rn.f32x2 %0, %1, %2, %3;" : "=l"(d) : "l"(a), "l"(b), "l"(c))
#define SPLAT2(d, s) \
    asm("mov.b64 %0, {%1, %1};" : "=l"(d) : "f"(s))
#define PACKF2(d, lo, hi) \
    asm("mov.b64 %0, {%1, %2};" : "=l"(d) : "f"(lo), "f"(hi))
#define UNPACK2(lo, hi, v) \
    asm("mov.b64 {%0, %1}, %2;" : "=f"(lo), "=f"(hi) : "l"(v))

// Scratch (device globals — no allocation allowed)
// M_g permuted per node (float4 units): idx = node*64 + l4*16 + k  -> M[k][4*l4..]
__device__ __align__(16) float E_g[NODES * K_ * K_];
__device__ __align__(16) float M_g[NODES * K_ * K_];
__device__ __align__(16) float u_g[NODES * K_];
__device__ __align__(16) float t_g[NODES * K_];   // t_j = M_j u_j
__device__ __align__(16) float c_g[NODES];        // c_j = u_j . t_j
// per-j-tile partial sums (8 j-tiles): [jt][node][k]
__device__ __align__(16) float S1p[8 * NODES * K_];
__device__ __align__(16) float S2p[8 * NODES * K_];
__device__ __align__(16) float S3p[8 * NODES];

// ---------------------------------------------------------------------------
// Warp-cooperative 16x16 matmul on PST-strided row-major smem, f32x2 FMAs.
// D = S1 * S2 (+ acc init). Lane owns row r = lane>>1, cols cb..cb+7.
// ---------------------------------------------------------------------------
__device__ __forceinline__ void warp_mm(const float* __restrict__ S1,
                                        const float* __restrict__ S2,
                                        float* __restrict__ D,
                                        int r, int cb, float* acc)
{
    float row[16];
    {
        const float4* rp = (const float4*)(S1 + r * PST);
        float4 r0 = rp[0], r1 = rp[1], r2 = rp[2], r3 = rp[3];
        row[0]=r0.x; row[1]=r0.y; row[2]=r0.z; row[3]=r0.w;
        row[4]=r1.x; row[5]=r1.y; row[6]=r1.z; row[7]=r1.w;
        row[8]=r2.x; row[9]=r2.y; row[10]=r2.z; row[11]=r2.w;
        row[12]=r3.x; row[13]=r3.y; row[14]=r3.z; row[15]=r3.w;
    }
    unsigned long long acc2[4];
    PACKF2(acc2[0], acc[0], acc[1]);
    PACKF2(acc2[1], acc[2], acc[3]);
    PACKF2(acc2[2], acc[4], acc[5]);
    PACKF2(acc2[3], acc[6], acc[7]);
    #pragma unroll
    for (int l = 0; l < 16; l++) {
        const ulonglong2* bp = (const ulonglong2*)(S2 + l*PST + cb);
        const ulonglong2 bq = bp[0];
        const ulonglong2 br = bp[1];
        unsigned long long rl; SPLAT2(rl, row[l]);
        FMA2(acc2[0], rl, bq.x, acc2[0]);
        FMA2(acc2[1], rl, bq.y, acc2[1]);
        FMA2(acc2[2], rl, br.x, acc2[2]);
        FMA2(acc2[3], rl, br.y, acc2[3]);
    }
    *(ulonglong2*)(D + r*PST + cb)     = make_ulonglong2(acc2[0], acc2[1]);
    *(ulonglong2*)(D + r*PST + cb + 4) = make_ulonglong2(acc2[2], acc2[3]);
    UNPACK2(acc[0], acc[1], acc2[0]);
    UNPACK2(acc[2], acc[3], acc2[1]);
    UNPACK2(acc[4], acc[5], acc2[2]);
    UNPACK2(acc[6], acc[7], acc2[3]);
    __syncwarp();
}

// ---------------------------------------------------------------------------
// Kernel 1: warp-per-node expm precompute (padded shared, f32x2).
// Outputs E, M (permuted), u = E^T mu, t = M u, c = u.t
// ---------------------------------------------------------------------------
__global__ __launch_bounds__(128, 2)
void prep_kernel(const float* __restrict__ mu_q,
                 const float* __restrict__ sigma_q,
                 const float* __restrict__ phi,
                 const float* __restrict__ gen)
{
    const int lane = threadIdx.x & 31;
    const int wrp  = threadIdx.x >> 5;
    const int node = blockIdx.x * WPB + wrp;
    const int r    = lane >> 1;
    const int cb   = (lane & 1) * 8;

    __shared__ __align__(16) float sm[WPB * 1024];
    float* P0 = sm + wrp * 1024;        // A        (16 x PST)
    float* P1 = P0 + 320;               // slot 1
    float* P2 = P0 + 640;               // slot 2
    float* dv = P0 + 960;               // dinv[16]
    float* mh = P0 + 976;               // mu[16]
    float* um = P0 + 992;               // u[16]
    float* tm = P0 + 1008;              // t[16]

    // ---- build A ----
    const float q0 = __ldg(&phi[node*3 + 0]);
    const float q1 = __ldg(&phi[node*3 + 1]);
    const float q2 = __ldg(&phi[node*3 + 2]);
    const int gi = r * 16 + cb;
    float a[8];
    {
        const float4 g00 = __ldg((const float4*)(gen + gi));
        const float4 g01 = __ldg((const float4*)(gen + gi + 4));
        const float4 g10 = __ldg((const float4*)(gen + 256 + gi));
        const float4 g11 = __ldg((const float4*)(gen + 256 + gi + 4));
        const float4 g20 = __ldg((const float4*)(gen + 512 + gi));
        const float4 g21 = __ldg((const float4*)(gen + 512 + gi + 4));
        a[0] = q0*g00.x + q1*g10.x + q2*g20.x;
        a[1] = q0*g00.y + q1*g10.y + q2*g20.y;
        a[2] = q0*g00.z + q1*g10.z + q2*g20.z;
        a[3] = q0*g00.w + q1*g10.w + q2*g20.w;
        a[4] = q0*g01.x + q1*g11.x + q2*g21.x;
        a[5] = q0*g01.y + q1*g11.y + q2*g21.y;
        a[6] = q0*g01.z + q1*g11.z + q2*g21.z;
        a[7] = q0*g01.w + q1*g11.w + q2*g21.w;
    }

    // ---- inf-norm via shfl ----
    float s = fabsf(a[0]) + fabsf(a[1]) + fabsf(a[2]) + fabsf(a[3])
            + fabsf(a[4]) + fabsf(a[5]) + fabsf(a[6]) + fabsf(a[7]);
    s += __shfl_xor_sync(0xffffffffu, s, 1);
    float mx = s;
    mx = fmaxf(mx, __shfl_xor_sync(0xffffffffu, mx, 2));
    mx = fmaxf(mx, __shfl_xor_sync(0xffffffffu, mx, 4));
    mx = fmaxf(mx, __shfl_xor_sync(0xffffffffu, mx, 8));
    mx = fmaxf(mx, __shfl_xor_sync(0xffffffffu, mx, 16));
    int s_sq = 0;
    while (mx > 1.0f && s_sq < 30) { mx *= 0.5f; s_sq++; }
    const float sc = ldexpf(1.0f, -s_sq);
    #pragma unroll
    for (int e = 0; e < 8; e++) a[e] *= sc;
    *(float4*)(P0 + r*PST + cb)     = make_float4(a[0], a[1], a[2], a[3]);
    *(float4*)(P0 + r*PST + cb + 4) = make_float4(a[4], a[5], a[6], a[7]);
    if (lane < 16) {
        const float sq = fmaxf(__ldg(&sigma_q[node*16 + lane]), EPS);
        dv[lane] = 1.0f / (sq + EPS);
        mh[lane] = __ldg(&mu_q[node*16 + lane]);
    }
    __syncwarp();

    // ---- A2 -> P1, A4 -> P2 ----
    float a2own[8] = {0,0,0,0,0,0,0,0};
    warp_mm(P0, P0, P1, r, cb, a2own);
    float a4own[8] = {0,0,0,0,0,0,0,0};
    warp_mm(P1, P1, P2, r, cb, a4own);

    // ---- tails (f32x2 double-stream dot) ----
    float even[8], odd[8];
    {
        float row[16];
        {
            const float4* rp = (const float4*)(P2 + r * PST);
            float4 r0 = rp[0], r1 = rp[1], r2 = rp[2], r3 = rp[3];
            row[0]=r0.x; row[1]=r0.y; row[2]=r0.z; row[3]=r0.w;
            row[4]=r1.x; row[5]=r1.y; row[6]=r1.z; row[7]=r1.w;
            row[8]=r2.x; row[9]=r2.y; row[10]=r2.z; row[11]=r2.w;
            row[12]=r3.x; row[13]=r3.y; row[14]=r3.z; row[15]=r3.w;
        }
        unsigned long long s2a[4], s4a[4];
        {
            unsigned long long z; SPLAT2(z, 0.0f);
            s2a[0]=z; s2a[1]=z; s2a[2]=z; s2a[3]=z;
            s4a[0]=z; s4a[1]=z; s4a[2]=z; s4a[3]=z;
        }
        #pragma unroll
        for (int l = 0; l < 16; l++) {
            const ulonglong2* bp = (const ulonglong2*)(P1 + l*PST + cb);
            const ulonglong2 bq = bp[0];
            const ulonglong2 br = bp[1];
            const ulonglong2* dp = (const ulonglong2*)(P2 + l*PST + cb);
            const ulonglong2 dq = dp[0];
            const ulonglong2 dr = dp[1];
            unsigned long long rl; SPLAT2(rl, row[l]);
            FMA2(s2a[0], rl, bq.x, s2a[0]);
            FMA2(s2a[1], rl, bq.y, s2a[1]);
            FMA2(s2a[2], rl, br.x, s2a[2]);
            FMA2(s2a[3], rl, br.y, s2a[3]);
            FMA2(s4a[0], rl, dq.x, s4a[0]);
            FMA2(s4a[1], rl, dq.y, s4a[1]);
            FMA2(s4a[2], rl, dr.x, s4a[2]);
            FMA2(s4a[3], rl, dr.y, s4a[3]);
        }
        float S2e[8], S4e[8];
        UNPACK2(S2e[0], S2e[1], s2a[0]); UNPACK2(S2e[2], S2e[3], s2a[1]);
        UNPACK2(S2e[4], S2e[5], s2a[2]); UNPACK2(S2e[6], S2e[7], s2a[3]);
        UNPACK2(S4e[0], S4e[1], s4a[0]); UNPACK2(S4e[2], S4e[3], s4a[1]);
        UNPACK2(S4e[4], S4e[5], s4a[2]); UNPACK2(S4e[6], S4e[7], s4a[3]);
        #pragma unroll
        for (int e = 0; e < 8; e++) {
            const float idn = (r == cb + e) ? 1.0f : 0.0f;
            even[e] = idn + 0.5f        * a2own[e] + (1.0f/24.0f)  * a4own[e]
                          + (1.0f/720.0f)  * S2e[e] + (1.0f/40320.0f)  * S4e[e];
            odd[e]  = idn + (1.0f/6.0f) * a2own[e] + (1.0f/120.0f) * a4own[e]
                          + (1.0f/5040.0f) * S2e[e] + (1.0f/362880.0f) * S4e[e];
        }
    }
    __syncwarp();
    *(float4*)(P1 + r*PST + cb)     = make_float4(odd[0], odd[1], odd[2], odd[3]);
    *(float4*)(P1 + r*PST + cb + 4) = make_float4(odd[4], odd[5], odd[6], odd[7]);
    __syncwarp();

    // ---- E = even + A * odd -> P2 ----
    warp_mm(P0, P1, P2, r, cb, even);

    // ---- squarings ----
    float* Xp = P2;
    float* Yp = P1;
    for (int t = 0; t < s_sq; t++) {
        float acc[8] = {0,0,0,0,0,0,0,0};
        warp_mm(Xp, Xp, Yp, r, cb, acc);
        float* tmp = Xp; Xp = Yp; Yp = tmp;
    }
    // Xp holds E (row-major, stride PST).

    // ---- u[k] = col k of E . mu ----
    if (lane < 16) {
        float uu = 0.f;
        #pragma unroll
        for (int l = 0; l < 16; l++) uu = fmaf(Xp[l*PST + lane], mh[l], uu);
        um[lane] = uu;
        u_g[node*16 + lane] = uu;
    }
    __syncwarp();

    // ---- M[r][cb+e] = sum_l E[l][r] dinv[l] E[l][cb+e];  t = M u;  c = u.t ----
    {
        unsigned long long ma[4];
        { unsigned long long z; SPLAT2(z, 0.0f); ma[0]=z; ma[1]=z; ma[2]=z; ma[3]=z; }
        #pragma unroll
        for (int l = 0; l < 16; l++) {
            const float w = Xp[l*PST + r] * dv[l];
            const ulonglong2* ep = (const ulonglong2*)(Xp + l*PST + cb);
            const ulonglong2 eq = ep[0];
            const ulonglong2 er = ep[1];
            unsigned long long wl; SPLAT2(wl, w);
            FMA2(ma[0], wl, eq.x, ma[0]);
            FMA2(ma[1], wl, eq.y, ma[1]);
            FMA2(ma[2], wl, er.x, ma[2]);
            FMA2(ma[3], wl, er.y, ma[3]);
        }
        float m[8];
        UNPACK2(m[0], m[1], ma[0]); UNPACK2(m[2], m[3], ma[1]);
        UNPACK2(m[4], m[5], ma[2]); UNPACK2(m[6], m[7], ma[3]);

        float4* Md = ((float4*)M_g) + node*64;
        Md[(cb >> 2)*16 + r]       = make_float4(m[0], m[1], m[2], m[3]);
        Md[((cb >> 2) + 1)*16 + r] = make_float4(m[4], m[5], m[6], m[7]);

        *(float4*)(E_g + node*256 + r*16 + cb)     = *(const float4*)(Xp + r*PST + cb);
        *(float4*)(E_g + node*256 + r*16 + cb + 4) = *(const float4*)(Xp + r*PST + cb + 4);

        float tp = 0.f;
        #pragma unroll
        for (int e = 0; e < 8; e++) tp = fmaf(m[e], um[cb + e], tp);
        tp += __shfl_xor_sync(0xffffffffu, tp, 1);
        if ((lane & 1) == 0) {
            tm[r] = tp;
            t_g[node*16 + r] = tp;
        }
    }
    __syncwarp();
    {
        float pc = um[lane & 15] * tm[lane & 15];
        pc += __shfl_xor_sync(0xffffffffu, pc, 1);
        pc += __shfl_xor_sync(0xffffffffu, pc, 2);
        pc += __shfl_xor_sync(0xffffffffu, pc, 4);
        pc += __shfl_xor_sync(0xffffffffu, pc, 8);
        if (lane == 0) c_g[node] = pc;
    }
}

// ---------------------------------------------------------------------------
// Kernel 2: pair partial sums (f32x2 dot core; structure = protected R12 win).
// Block = (b, i-tile of 8, j-tile of 16), 256 threads = (jl, k).
// ---------------------------------------------------------------------------
__global__ __launch_bounds__(256, 4)
void pair_partial(const float* __restrict__ beta)
{
    const int blk = blockIdx.x;        // 0..1023
    const int b   = blk >> 7;
    const int it  = (blk >> 3) & 15;
    const int jt  = blk & 7;
    const int i0  = it * 8;
    const int j0  = jt * 16;
    const int tid = threadIdx.x;
    const int jl  = tid >> 4;          // 0..15
    const int k   = tid & 15;
    const int j   = j0 + jl;

    __shared__ __align__(16) float us[8][16];    // u_i tile
    __shared__ float bs[8][16];                  // beta tile [i][jl]
    __shared__ float sm1[16][8][16];             // 8 KB [jl][i][k]
    __shared__ float sm2[16][8][16];             // 8 KB
    __shared__ float sm3[16][8];

    if (tid < 32) ((float4*)us)[tid] = __ldg(((const float4*)(u_g + (b*N_ + i0)*K_)) + tid);
    if (tid < 128) {
        const int ii = tid >> 4, jj = tid & 15;
        bs[ii][jj] = __ldg(&beta[(b*N_ + i0 + ii)*N_ + j0 + jj]);
    }
    __syncthreads();

    // M row k of M_j as 8 packed f32 pairs
    const ulonglong2* Mj2 = (const ulonglong2*)(((const float4*)M_g) + (b*N_ + j)*64 + k);
    const ulonglong2 q0 = Mj2[0];      // cols 0-3
    const ulonglong2 q1 = Mj2[16];     // cols 4-7
    const ulonglong2 q2 = Mj2[32];     // cols 8-11
    const ulonglong2 q3 = Mj2[48];     // cols 12-15
    const float tjk = __ldg(&t_g[(b*N_ + j)*K_ + k]);
    const float cj  = __ldg(&c_g[b*N_ + j]);

    #pragma unroll
    for (int ii = 0; ii < 8; ii++) {
        const ulonglong2* up = (const ulonglong2*)us[ii];
        const ulonglong2 u0 = up[0], u1 = up[1];

        unsigned long long acc2; SPLAT2(acc2, 0.0f);
        FMA2(acc2, q0.x, u0.x, acc2);
        FMA2(acc2, q0.y, u0.y, acc2);
        FMA2(acc2, q1.x, u1.x, acc2);
        FMA2(acc2, q1.y, u1.y, acc2);
        const ulonglong2 u2 = up[2], u3 = up[3];
        FMA2(acc2, q2.x, u2.x, acc2);
        FMA2(acc2, q2.y, u2.y, acc2);
        FMA2(acc2, q3.x, u3.x, acc2);
        FMA2(acc2, q3.y, u3.y, acc2);
        float alo, ahi; UNPACK2(alo, ahi, acc2);
        const float a = alo + ahi;

        const float uik = us[ii][k];
        float p = uik * fmaf(0.5f, a, -tjk);
        p += __shfl_xor_sync(0xffffffffu, p, 8);
        p += __shfl_xor_sync(0xffffffffu, p, 4);
        p += __shfl_xor_sync(0xffffffffu, p, 2);
        p += __shfl_xor_sync(0xffffffffu, p, 1);
        const float kl  = p + 0.5f * cj;
        const float bj  = bs[ii][jl];
        const float bkl = bj * kl;
        const float v   = a - tjk;
        sm1[jl][ii][k] = bj  * v;
        sm2[jl][ii][k] = bkl * v;
        if (k == 0) sm3[jl][ii] = bkl;
    }
    __syncthreads();

    if (tid < 128) {
        const int ii = tid >> 4, kk = tid & 15;
        float q1r = 0.f, q2r = 0.f;
        #pragma unroll
        for (int jj = 0; jj < 16; jj++) {
            q1r += sm1[jj][ii][kk];
            q2r += sm2[jj][ii][kk];
        }
        const int node = b*N_ + i0 + ii;
        S1p[jt*16384 + node*16 + kk] = q1r;
        S2p[jt*16384 + node*16 + kk] = q2r;
    } else if (tid < 136) {
        const int ii = tid - 128;
        float q3r = 0.f;
        #pragma unroll
        for (int jj = 0; jj < 16; jj++) q3r += sm3[jj][ii];
        S3p[jt*1024 + b*N_ + i0 + ii] = q3r;
    }
}

// ---------------------------------------------------------------------------
// Kernel 3: finish (structure = protected R12 win).
// ---------------------------------------------------------------------------
__global__ __launch_bounds__(256)
void finish_kernel(const float* __restrict__ mu_q,
                   const float* __restrict__ sigma_q,
                   const float* __restrict__ mu_p,
                   const float* __restrict__ sigma_p,
                   float* __restrict__ out)
{
    const int tid  = threadIdx.x;
    const int n    = tid >> 4, k = tid & 15;
    const int node = blockIdx.x * 16 + n;

    __shared__ float tv[16][17];

    float S1 = 0.f, S2 = 0.f, S3 = 0.f;
    #pragma unroll
    for (int jt = 0; jt < 8; jt++) {
        S1 += S1p[jt*16384 + node*16 + k];
        S2 += S2p[jt*16384 + node*16 + k];
        S3 += S3p[jt*1024 + node];
    }
    tv[n][k] = LAM * S1 + (LAM / KAPPA) * (S2 - S3 * S1);
    __syncthreads();

    const float4* Ei = (const float4*)(E_g + node*256 + k*16);
    const float4 e0 = __ldg(Ei), e1 = __ldg(Ei+1), e2 = __ldg(Ei+2), e3 = __ldg(Ei+3);
    float g = e0.x * tv[n][0];
    g = fmaf(e0.y, tv[n][1],  g); g = fmaf(e0.z, tv[n][2],  g); g = fmaf(e0.w, tv[n][3],  g);
    g = fmaf(e1.x, tv[n][4],  g); g = fmaf(e1.y, tv[n][5],  g); g = fmaf(e1.z, tv[n][6],  g); g = fmaf(e1.w, tv[n][7],  g);
    g = fmaf(e2.x, tv[n][8],  g); g = fmaf(e2.y, tv[n][9],  g); g = fmaf(e2.z, tv[n][10], g); g = fmaf(e2.w, tv[n][11], g);
    g = fmaf(e3.x, tv[n][12], g); g = fmaf(e3.y, tv[n][13], g); g = fmaf(e3.z, tv[n][14], g); g = fmaf(e3.w, tv[n][15], g);

    const float sp = fmaxf(__ldg(&sigma_p[node*16 + k]), EPS);
    const float sq = fmaxf(__ldg(&sigma_q[node*16 + k]), EPS);
    const float dm = __ldg(&mu_q[node*16 + k]) - __ldg(&mu_p[node*16 + k]);

    out[node*16 + k]            = g + ALPHA * dm / sp;
    out[NODES*K_ + node*16 + k] = ALPHA * 0.5f * (1.0f / sp - 1.0f / sq);
}

extern "C" void kernel_launch(void* const* d_in, const int* in_sizes, int n_in,
                              void* d_out, int out_size)
{
    const float* mu_q    = (const float*)d_in[0];
    const float* sigma_q = (const float*)d_in[1];
    const float* mu_p    = (const float*)d_in[2];
    const float* sigma_p = (const float*)d_in[3];
    const float* beta    = (const float*)d_in[4];
    const float* phi     = (const float*)d_in[5];
    const float* gen     = (const float*)d_in[6];
    float* out = (float*)d_out;

    prep_kernel<<<NODES / WPB, 128>>>(mu_q, sigma_q, phi, gen);
    pair_partial<<<NODES, 256>>>(beta);
    finish_kernel<<<NODES / 16, 256>>>(mu_q, sigma_q, mu_p, sigma_p, out);
}

// round 16
// speedup vs baseline: 1.0980x; 1.0980x over previous
#include <cuda_runtime.h>
#include <cuda_bf16.h>
#include <math.h>

// Problem constants
#define B_    8
#define N_    128
#define K_    16
#define ALPHA 0.01f
#define LAM   1.0f
#define KAPPA 1.0f
#define EPS   1e-6f

#define NODES (B_ * N_)   // 1024
#define WPB   4           // warps (nodes) per block in prep
#define PST   20          // padded row stride (floats) for prep matrices
#define THETA 1.5f        // scaling threshold (Taylor-9 err ~1.6e-5, budget 1e-3)

// Scratch (device globals — no allocation allowed)
// M_g permuted per node (float4 units): idx = node*64 + l4*16 + k  -> M[k][4*l4..]
__device__ __align__(16) float E_g[NODES * K_ * K_];
__device__ __align__(16) float M_g[NODES * K_ * K_];
__device__ __align__(16) float u_g[NODES * K_];
__device__ __align__(16) float t_g[NODES * K_];   // t_j = M_j u_j
__device__ __align__(16) float c_g[NODES];        // c_j = u_j . t_j
// per-j-tile partial sums (8 j-tiles): [jt][node][k]
__device__ __align__(16) float S1p[8 * NODES * K_];
__device__ __align__(16) float S2p[8 * NODES * K_];
__device__ __align__(16) float S3p[8 * NODES];

// ---------------------------------------------------------------------------
// Warp-cooperative 16x16 matmul on PST-strided row-major smem:
// D = S1 * S2 (+ acc init). Lane owns row r = lane>>1, cols cb..cb+7.
// PST=20 -> row starts hit 8 distinct banks (2-way max conflict).
// ---------------------------------------------------------------------------
__device__ __forceinline__ void warp_mm(const float* __restrict__ S1,
                                        const float* __restrict__ S2,
                                        float* __restrict__ D,
                                        int r, int cb, float* acc)
{
    float row[16];
    {
        const float4* rp = (const float4*)(S1 + r * PST);
        float4 r0 = rp[0], r1 = rp[1], r2 = rp[2], r3 = rp[3];
        row[0]=r0.x; row[1]=r0.y; row[2]=r0.z; row[3]=r0.w;
        row[4]=r1.x; row[5]=r1.y; row[6]=r1.z; row[7]=r1.w;
        row[8]=r2.x; row[9]=r2.y; row[10]=r2.z; row[11]=r2.w;
        row[12]=r3.x; row[13]=r3.y; row[14]=r3.z; row[15]=r3.w;
    }
    #pragma unroll
    for (int l = 0; l < 16; l++) {
        const float4 b0 = *(const float4*)(S2 + l*PST + cb);
        const float4 b1 = *(const float4*)(S2 + l*PST + cb + 4);
        acc[0] = fmaf(row[l], b0.x, acc[0]);
        acc[1] = fmaf(row[l], b0.y, acc[1]);
        acc[2] = fmaf(row[l], b0.z, acc[2]);
        acc[3] = fmaf(row[l], b0.w, acc[3]);
        acc[4] = fmaf(row[l], b1.x, acc[4]);
        acc[5] = fmaf(row[l], b1.y, acc[5]);
        acc[6] = fmaf(row[l], b1.z, acc[6]);
        acc[7] = fmaf(row[l], b1.w, acc[7]);
    }
    *(float4*)(D + r*PST + cb)     = make_float4(acc[0], acc[1], acc[2], acc[3]);
    *(float4*)(D + r*PST + cb + 4) = make_float4(acc[4], acc[5], acc[6], acc[7]);
    __syncwarp();
}

// ---------------------------------------------------------------------------
// Kernel 1: warp-per-node expm precompute (padded shared).
// Outputs E, M (permuted), u = E^T mu, t = M u, c = u.t
// ---------------------------------------------------------------------------
__global__ __launch_bounds__(128, 2)
void prep_kernel(const float* __restrict__ mu_q,
                 const float* __restrict__ sigma_q,
                 const float* __restrict__ phi,
                 const float* __restrict__ gen)
{
    const int lane = threadIdx.x & 31;
    const int wrp  = threadIdx.x >> 5;
    const int node = blockIdx.x * WPB + wrp;
    const int r    = lane >> 1;
    const int cb   = (lane & 1) * 8;

    __shared__ __align__(16) float sm[WPB * 1024];
    float* P0 = sm + wrp * 1024;        // A        (16 x PST)
    float* P1 = P0 + 320;               // slot 1
    float* P2 = P0 + 640;               // slot 2
    float* dv = P0 + 960;               // dinv[16]
    float* mh = P0 + 976;               // mu[16]
    float* um = P0 + 992;               // u[16]
    float* tm = P0 + 1008;              // t[16]

    // ---- build A ----
    const float q0 = __ldg(&phi[node*3 + 0]);
    const float q1 = __ldg(&phi[node*3 + 1]);
    const float q2 = __ldg(&phi[node*3 + 2]);
    const int gi = r * 16 + cb;
    float a[8];
    {
        const float4 g00 = __ldg((const float4*)(gen + gi));
        const float4 g01 = __ldg((const float4*)(gen + gi + 4));
        const float4 g10 = __ldg((const float4*)(gen + 256 + gi));
        const float4 g11 = __ldg((const float4*)(gen + 256 + gi + 4));
        const float4 g20 = __ldg((const float4*)(gen + 512 + gi));
        const float4 g21 = __ldg((const float4*)(gen + 512 + gi + 4));
        a[0] = q0*g00.x + q1*g10.x + q2*g20.x;
        a[1] = q0*g00.y + q1*g10.y + q2*g20.y;
        a[2] = q0*g00.z + q1*g10.z + q2*g20.z;
        a[3] = q0*g00.w + q1*g10.w + q2*g20.w;
        a[4] = q0*g01.x + q1*g11.x + q2*g21.x;
        a[5] = q0*g01.y + q1*g11.y + q2*g21.y;
        a[6] = q0*g01.z + q1*g11.z + q2*g21.z;
        a[7] = q0*g01.w + q1*g11.w + q2*g21.w;
    }

    // ---- inf-norm via shfl ----
    float s = fabsf(a[0]) + fabsf(a[1]) + fabsf(a[2]) + fabsf(a[3])
            + fabsf(a[4]) + fabsf(a[5]) + fabsf(a[6]) + fabsf(a[7]);
    s += __shfl_xor_sync(0xffffffffu, s, 1);
    float mx = s;
    mx = fmaxf(mx, __shfl_xor_sync(0xffffffffu, mx, 2));
    mx = fmaxf(mx, __shfl_xor_sync(0xffffffffu, mx, 4));
    mx = fmaxf(mx, __shfl_xor_sync(0xffffffffu, mx, 8));
    mx = fmaxf(mx, __shfl_xor_sync(0xffffffffu, mx, 16));
    int s_sq = 0;
    while (mx > THETA && s_sq < 30) { mx *= 0.5f; s_sq++; }
    const float sc = ldexpf(1.0f, -s_sq);
    #pragma unroll
    for (int e = 0; e < 8; e++) a[e] *= sc;
    *(float4*)(P0 + r*PST + cb)     = make_float4(a[0], a[1], a[2], a[3]);
    *(float4*)(P0 + r*PST + cb + 4) = make_float4(a[4], a[5], a[6], a[7]);
    if (lane < 16) {
        const float sq = fmaxf(__ldg(&sigma_q[node*16 + lane]), EPS);
        dv[lane] = 1.0f / (sq + EPS);
        mh[lane] = __ldg(&mu_q[node*16 + lane]);
    }
    __syncwarp();

    // ---- A2 -> P1, A4 -> P2 ----
    float a2own[8] = {0,0,0,0,0,0,0,0};
    warp_mm(P0, P0, P1, r, cb, a2own);
    float a4own[8] = {0,0,0,0,0,0,0,0};
    warp_mm(P1, P1, P2, r, cb, a4own);

    // ---- tails ----
    float even[8], odd[8];
    {
        float row[16];
        {
            const float4* rp = (const float4*)(P2 + r * PST);
            float4 r0 = rp[0], r1 = rp[1], r2 = rp[2], r3 = rp[3];
            row[0]=r0.x; row[1]=r0.y; row[2]=r0.z; row[3]=r0.w;
            row[4]=r1.x; row[5]=r1.y; row[6]=r1.z; row[7]=r1.w;
            row[8]=r2.x; row[9]=r2.y; row[10]=r2.z; row[11]=r2.w;
            row[12]=r3.x; row[13]=r3.y; row[14]=r3.z; row[15]=r3.w;
        }
        float S2e[8] = {0,0,0,0,0,0,0,0};
        float S4e[8] = {0,0,0,0,0,0,0,0};
        #pragma unroll
        for (int l = 0; l < 16; l++) {
            const float4 b0 = *(const float4*)(P1 + l*PST + cb);
            const float4 b1 = *(const float4*)(P1 + l*PST + cb + 4);
            const float4 d0 = *(const float4*)(P2 + l*PST + cb);
            const float4 d1 = *(const float4*)(P2 + l*PST + cb + 4);
            S2e[0]=fmaf(row[l],b0.x,S2e[0]); S2e[1]=fmaf(row[l],b0.y,S2e[1]);
            S2e[2]=fmaf(row[l],b0.z,S2e[2]); S2e[3]=fmaf(row[l],b0.w,S2e[3]);
            S2e[4]=fmaf(row[l],b1.x,S2e[4]); S2e[5]=fmaf(row[l],b1.y,S2e[5]);
            S2e[6]=fmaf(row[l],b1.z,S2e[6]); S2e[7]=fmaf(row[l],b1.w,S2e[7]);
            S4e[0]=fmaf(row[l],d0.x,S4e[0]); S4e[1]=fmaf(row[l],d0.y,S4e[1]);
            S4e[2]=fmaf(row[l],d0.z,S4e[2]); S4e[3]=fmaf(row[l],d0.w,S4e[3]);
            S4e[4]=fmaf(row[l],d1.x,S4e[4]); S4e[5]=fmaf(row[l],d1.y,S4e[5]);
            S4e[6]=fmaf(row[l],d1.z,S4e[6]); S4e[7]=fmaf(row[l],d1.w,S4e[7]);
        }
        #pragma unroll
        for (int e = 0; e < 8; e++) {
            const float idn = (r == cb + e) ? 1.0f : 0.0f;
            even[e] = idn + 0.5f        * a2own[e] + (1.0f/24.0f)  * a4own[e]
                          + (1.0f/720.0f)  * S2e[e] + (1.0f/40320.0f)  * S4e[e];
            odd[e]  = idn + (1.0f/6.0f) * a2own[e] + (1.0f/120.0f) * a4own[e]
                          + (1.0f/5040.0f) * S2e[e] + (1.0f/362880.0f) * S4e[e];
        }
    }
    __syncwarp();
    *(float4*)(P1 + r*PST + cb)     = make_float4(odd[0], odd[1], odd[2], odd[3]);
    *(float4*)(P1 + r*PST + cb + 4) = make_float4(odd[4], odd[5], odd[6], odd[7]);
    __syncwarp();

    // ---- E = even + A * odd -> P2 ----
    warp_mm(P0, P1, P2, r, cb, even);

    // ---- squarings ----
    float* Xp = P2;
    float* Yp = P1;
    for (int t = 0; t < s_sq; t++) {
        float acc[8] = {0,0,0,0,0,0,0,0};
        warp_mm(Xp, Xp, Yp, r, cb, acc);
        float* tmp = Xp; Xp = Yp; Yp = tmp;
    }
    // Xp holds E (row-major, stride PST).

    // ---- u[k] = col k of E . mu ----
    if (lane < 16) {
        float uu = 0.f;
        #pragma unroll
        for (int l = 0; l < 16; l++) uu = fmaf(Xp[l*PST + lane], mh[l], uu);
        um[lane] = uu;
        u_g[node*16 + lane] = uu;
    }
    __syncwarp();

    // ---- M[r][cb+e] = sum_l E[l][r] dinv[l] E[l][cb+e];  t = M u;  c = u.t ----
    {
        float m[8] = {0,0,0,0,0,0,0,0};
        #pragma unroll
        for (int l = 0; l < 16; l++) {
            const float w = Xp[l*PST + r] * dv[l];
            const float4 e0 = *(const float4*)(Xp + l*PST + cb);
            const float4 e1 = *(const float4*)(Xp + l*PST + cb + 4);
            m[0]=fmaf(w,e0.x,m[0]); m[1]=fmaf(w,e0.y,m[1]);
            m[2]=fmaf(w,e0.z,m[2]); m[3]=fmaf(w,e0.w,m[3]);
            m[4]=fmaf(w,e1.x,m[4]); m[5]=fmaf(w,e1.y,m[5]);
            m[6]=fmaf(w,e1.z,m[6]); m[7]=fmaf(w,e1.w,m[7]);
        }
        float4* Md = ((float4*)M_g) + node*64;
        Md[(cb >> 2)*16 + r]       = make_float4(m[0], m[1], m[2], m[3]);
        Md[((cb >> 2) + 1)*16 + r] = make_float4(m[4], m[5], m[6], m[7]);

        *(float4*)(E_g + node*256 + r*16 + cb)     = *(const float4*)(Xp + r*PST + cb);
        *(float4*)(E_g + node*256 + r*16 + cb + 4) = *(const float4*)(Xp + r*PST + cb + 4);

        float tp = 0.f;
        #pragma unroll
        for (int e = 0; e < 8; e++) tp = fmaf(m[e], um[cb + e], tp);
        tp += __shfl_xor_sync(0xffffffffu, tp, 1);
        if ((lane & 1) == 0) {
            tm[r] = tp;
            t_g[node*16 + r] = tp;
        }
    }
    __syncwarp();
    {
        float pc = um[lane & 15] * tm[lane & 15];
        pc += __shfl_xor_sync(0xffffffffu, pc, 1);
        pc += __shfl_xor_sync(0xffffffffu, pc, 2);
        pc += __shfl_xor_sync(0xffffffffu, pc, 4);
        pc += __shfl_xor_sync(0xffffffffu, pc, 8);
        if (lane == 0) c_g[node] = pc;
    }
}

// ---------------------------------------------------------------------------
// Kernel 2: pair partial sums (byte-identical to R14 — protected win).
// Block = (b, i-tile of 8, j-tile of 16), 256 threads = (jl, k).
// ---------------------------------------------------------------------------
__global__ __launch_bounds__(256, 4)
void pair_partial(const float* __restrict__ beta)
{
    const int blk = blockIdx.x;        // 0..1023
    const int b   = blk >> 7;
    const int it  = (blk >> 3) & 15;
    const int jt  = blk & 7;
    const int i0  = it * 8;
    const int j0  = jt * 16;
    const int tid = threadIdx.x;
    const int jl  = tid >> 4;          // 0..15
    const int k   = tid & 15;
    const int j   = j0 + jl;

    __shared__ __align__(16) float us[8][16];    // u_i tile
    __shared__ float bs[8][16];                  // beta tile [i][jl]
    __shared__ float sm1[16][8][16];             // 8 KB [jl][i][k]
    __shared__ float sm2[16][8][16];             // 8 KB
    __shared__ float sm3[16][8];

    if (tid < 32) ((float4*)us)[tid] = __ldg(((const float4*)(u_g + (b*N_ + i0)*K_)) + tid);
    if (tid < 128) {
        const int ii = tid >> 4, jj = tid & 15;
        bs[ii][jj] = __ldg(&beta[(b*N_ + i0 + ii)*N_ + j0 + jj]);
    }
    __syncthreads();

    const float4* Mj = ((const float4*)M_g) + (b*N_ + j)*64 + k;
    const float4 m0 = __ldg(Mj);
    const float4 m1 = __ldg(Mj + 16);
    const float4 m2 = __ldg(Mj + 32);
    const float4 m3 = __ldg(Mj + 48);
    const float tjk = __ldg(&t_g[(b*N_ + j)*K_ + k]);
    const float cj  = __ldg(&c_g[b*N_ + j]);

    #pragma unroll
    for (int ii = 0; ii < 8; ii++) {
        const float4* up = (const float4*)us[ii];
        const float4 u0 = up[0], u1 = up[1], u2 = up[2], u3 = up[3];

        float a = m0.x * u0.x;
        a = fmaf(m0.y, u0.y, a); a = fmaf(m0.z, u0.z, a); a = fmaf(m0.w, u0.w, a);
        a = fmaf(m1.x, u1.x, a); a = fmaf(m1.y, u1.y, a); a = fmaf(m1.z, u1.z, a); a = fmaf(m1.w, u1.w, a);
        a = fmaf(m2.x, u2.x, a); a = fmaf(m2.y, u2.y, a); a = fmaf(m2.z, u2.z, a); a = fmaf(m2.w, u2.w, a);
        a = fmaf(m3.x, u3.x, a); a = fmaf(m3.y, u3.y, a); a = fmaf(m3.z, u3.z, a); a = fmaf(m3.w, u3.w, a);

        const float uik = us[ii][k];
        float p = uik * fmaf(0.5f, a, -tjk);
        p += __shfl_xor_sync(0xffffffffu, p, 8);
        p += __shfl_xor_sync(0xffffffffu, p, 4);
        p += __shfl_xor_sync(0xffffffffu, p, 2);
        p += __shfl_xor_sync(0xffffffffu, p, 1);
        const float kl  = p + 0.5f * cj;
        const float bj  = bs[ii][jl];
        const float bkl = bj * kl;
        const float v   = a - tjk;
        sm1[jl][ii][k] = bj  * v;
        sm2[jl][ii][k] = bkl * v;
        if (k == 0) sm3[jl][ii] = bkl;
    }
    __syncthreads();

    if (tid < 128) {
        const int ii = tid >> 4, kk = tid & 15;
        float q1 = 0.f, q2 = 0.f;
        #pragma unroll
        for (int jj = 0; jj < 16; jj++) {
            q1 += sm1[jj][ii][kk];
            q2 += sm2[jj][ii][kk];
        }
        const int node = b*N_ + i0 + ii;
        S1p[jt*16384 + node*16 + kk] = q1;
        S2p[jt*16384 + node*16 + kk] = q2;
    } else if (tid < 136) {
        const int ii = tid - 128;
        float q3 = 0.f;
        #pragma unroll
        for (int jj = 0; jj < 16; jj++) q3 += sm3[jj][ii];
        S3p[jt*1024 + b*N_ + i0 + ii] = q3;
    }
}

// ---------------------------------------------------------------------------
// Kernel 3: finish (byte-identical to R14 — protected win).
// ---------------------------------------------------------------------------
__global__ __launch_bounds__(256)
void finish_kernel(const float* __restrict__ mu_q,
                   const float* __restrict__ sigma_q,
                   const float* __restrict__ mu_p,
                   const float* __restrict__ sigma_p,
                   float* __restrict__ out)
{
    const int tid  = threadIdx.x;
    const int n    = tid >> 4, k = tid & 15;
    const int node = blockIdx.x * 16 + n;

    __shared__ float tv[16][17];

    float S1 = 0.f, S2 = 0.f, S3 = 0.f;
    #pragma unroll
    for (int jt = 0; jt < 8; jt++) {
        S1 += S1p[jt*16384 + node*16 + k];
        S2 += S2p[jt*16384 + node*16 + k];
        S3 += S3p[jt*1024 + node];
    }
    tv[n][k] = LAM * S1 + (LAM / KAPPA) * (S2 - S3 * S1);
    __syncthreads();

    const float4* Ei = (const float4*)(E_g + node*256 + k*16);
    const float4 e0 = __ldg(Ei), e1 = __ldg(Ei+1), e2 = __ldg(Ei+2), e3 = __ldg(Ei+3);
    float g = e0.x * tv[n][0];
    g = fmaf(e0.y, tv[n][1],  g); g = fmaf(e0.z, tv[n][2],  g); g = fmaf(e0.w, tv[n][3],  g);
    g = fmaf(e1.x, tv[n][4],  g); g = fmaf(e1.y, tv[n][5],  g); g = fmaf(e1.z, tv[n][6],  g); g = fmaf(e1.w, tv[n][7],  g);
    g = fmaf(e2.x, tv[n][8],  g); g = fmaf(e2.y, tv[n][9],  g); g = fmaf(e2.z, tv[n][10], g); g = fmaf(e2.w, tv[n][11], g);
    g = fmaf(e3.x, tv[n][12], g); g = fmaf(e3.y, tv[n][13], g); g = fmaf(e3.z, tv[n][14], g); g = fmaf(e3.w, tv[n][15], g);

    const float sp = fmaxf(__ldg(&sigma_p[node*16 + k]), EPS);
    const float sq = fmaxf(__ldg(&sigma_q[node*16 + k]), EPS);
    const float dm = __ldg(&mu_q[node*16 + k]) - __ldg(&mu_p[node*16 + k]);

    out[node*16 + k]            = g + ALPHA * dm / sp;
    out[NODES*K_ + node*16 + k] = ALPHA * 0.5f * (1.0f / sp - 1.0f / sq);
}

extern "C" void kernel_launch(void* const* d_in, const int* in_sizes, int n_in,
                              void* d_out, int out_size)
{
    const float* mu_q    = (const float*)d_in[0];
    const float* sigma_q = (const float*)d_in[1];
    const float* mu_p    = (const float*)d_in[2];
    const float* sigma_p = (const float*)d_in[3];
    const float* beta    = (const float*)d_in[4];
    const float* phi     = (const float*)d_in[5];
    const float* gen     = (const float*)d_in[6];
    float* out = (float*)d_out;

    prep_kernel<<<NODES / WPB, 128>>>(mu_q, sigma_q, phi, gen);
    pair_partial<<<NODES, 256>>>(beta);
    finish_kernel<<<NODES / 16, 256>>>(mu_q, sigma_q, mu_p, sigma_p, out);
}